// round 5
// baseline (speedup 1.0000x reference)
#include <cuda_runtime.h>
#include <cstdint>
#include <cstddef>

#define Q    2048
#define NB   128
#define NBLK (Q/NB)

// ---------------- scratch (device globals; no allocations allowed) ----------
__device__ float  g_A[Q*Q];                 // working matrix / Cholesky factor
__device__ float  g_Linv[NBLK*NB*NB];       // per-panel inverse of diag block
__device__ float  g_X[(Q-NB)*NB];           // trsm staging buffer
__device__ float  g_w[Q];
__device__ int    g_cnt[Q];
__device__ float  g_v[Q];
__device__ float  g_sc[Q];
__device__ double g_red[4];                 // [0]=m'm [1]=sum r^2 [2]=sum log Lkk

// ---------------- reductions ----------------
__device__ __forceinline__ double block_reduce_1024(double v, double* scratch) {
  #pragma unroll
  for (int o = 16; o; o >>= 1) v += __shfl_down_sync(0xffffffffu, v, o);
  if ((threadIdx.x & 31) == 0) scratch[threadIdx.x >> 5] = v;
  __syncthreads();
  double r = 0.0;
  if (threadIdx.x < 32) {
    r = scratch[threadIdx.x];
    #pragma unroll
    for (int o = 16; o; o >>= 1) r += __shfl_down_sync(0xffffffffu, r, o);
  }
  __syncthreads();
  return r;   // valid on thread 0
}

// ---------------- small kernels ----------------
__global__ void k_reset() {
  int i = blockIdx.x * blockDim.x + threadIdx.x;
  if (i < Q) { g_w[i] = 0.f; g_cnt[i] = 0; }
  if (i < 4) g_red[i] = 0.0;
}

__global__ void k_obs(const float* __restrict__ yt, const float* __restrict__ yp,
                      const int* __restrict__ z,
                      const float* __restrict__ pe, const float* __restrict__ pb, int n) {
  int i = blockIdx.x * blockDim.x + threadIdx.x;
  float m = 0.f, r = 0.f;
  if (i < n) {
    r = yt[i] - yp[i];
    float s2 = pe[0] + pb[0];
    float u  = 0.5f * (erff(r / sqrtf(2.f * s2)) + 1.f);
    u = fminf(fmaxf(u, 1e-5f), 1.f - 1e-5f);
    m = erfinvf(2.f * u - 1.f) * 1.41421356237309515f;
    atomicAdd(&g_cnt[z[i]], 1);
    atomicAdd(&g_w[z[i]], m);
  }
  double mm = (double)m * (double)m;
  double rr = (double)r * (double)r;
  #pragma unroll
  for (int o = 16; o; o >>= 1) {
    mm += __shfl_down_sync(0xffffffffu, mm, o);
    rr += __shfl_down_sync(0xffffffffu, rr, o);
  }
  if ((threadIdx.x & 31) == 0) { atomicAdd(&g_red[0], mm); atomicAdd(&g_red[1], rr); }
}

__global__ void k_v() {
  int i = blockIdx.x * blockDim.x + threadIdx.x;
  if (i < Q) {
    int c = g_cnt[i];
    float sc = sqrtf((float)c);
    g_sc[i] = sc;
    g_v[i]  = (c > 0) ? g_w[i] / sc : 0.f;
  }
}

// A[i,j] = sqrt(c_i c_j) * sig2b * exp(-dist/(2 ell)) + (i==j) sig2e
__global__ void k_build(const float* __restrict__ dist, const float* __restrict__ pe,
                        const float* __restrict__ pb, const float* __restrict__ pl) {
  int idx = blockIdx.x * 256 + threadIdx.x;      // over Q*Q/4
  int i  = idx >> 9;                              // Q/4 = 512 float4 per row
  int j4 = idx & 511;
  float inv2l = 0.5f / pl[0];
  float sci = g_sc[i] * pb[0];
  int j = j4 * 4;
  float4 d = *(const float4*)(dist + (size_t)i * Q + j);
  float4 o;
  o.x = sci * g_sc[j + 0] * expf(-d.x * inv2l);
  o.y = sci * g_sc[j + 1] * expf(-d.y * inv2l);
  o.z = sci * g_sc[j + 2] * expf(-d.z * inv2l);
  o.w = sci * g_sc[j + 3] * expf(-d.w * inv2l);
  if (i >= j && i < j + 4) ((float*)&o)[i - j] += pe[0];
  *(float4*)(g_A + (size_t)i * Q + j) = o;
}

// ---------------- panel factorization: L11, inv(L11), logdet -------------
// 512 threads. smem: s[128*129], li[128*129], ls[32*100], dinv[128], lg[128]
extern __shared__ float sh[];

#define SPITCH 129

__global__ void k_potf(int k0, int kb) {
  float* s    = sh;                       // 128*129
  float* li   = sh + 128 * SPITCH;        // 128*129
  float* ls   = li + 128 * SPITCH;        // 32*100 transposed staging
  float* dinv = ls + 32 * 100;            // 128
  float* lg   = dinv + 128;               // 128
  int tid = threadIdx.x;
  int warp = tid >> 5, lane = tid & 31;

  for (int idx = tid; idx < 128 * 128; idx += 512) {
    int r = idx >> 7, c = idx & 127;
    s[r * SPITCH + c]  = g_A[(size_t)(k0 + r) * Q + k0 + c];
    li[r * SPITCH + c] = 0.f;
  }
  __syncthreads();

  #pragma unroll 1
  for (int p = 0; p < 4; p++) {
    int pc = p * 32;
    int nrows = 96 - pc;   // rows below this sub-panel within the 128 block

    // (a) warp 0 factors 32x32 diagonal sub-block in REGISTERS via shfl
    if (warp == 0) {
      float a[32];
      #pragma unroll
      for (int j = 0; j < 32; j++) a[j] = s[(pc + lane) * SPITCH + pc + j];
      #pragma unroll
      for (int j = 0; j < 32; j++) {
        float dj  = __shfl_sync(0xffffffffu, a[j], j);
        float d   = sqrtf(dj);
        float inv = 1.f / d;
        float lj  = (lane == j) ? d : a[j] * inv;
        a[j] = lj;
        #pragma unroll
        for (int k = j + 1; k < 32; k++) {
          float Lkj = __shfl_sync(0xffffffffu, a[j], k);
          if (lane >= k) a[k] -= lj * Lkj;
        }
      }
      #pragma unroll
      for (int j = 0; j < 32; j++)
        if (j <= lane) s[(pc + lane) * SPITCH + pc + j] = a[j];
      dinv[pc + lane] = 1.f / a[lane];
    }
    __syncthreads();

    // (b) warp 0: invert 32x32 diag sub-block (per-lane column, conflict-free)
    if (warp == 0) {
      int c = lane;
      #pragma unroll 1
      for (int r = c; r < 32; r++) {
        float acc = (r == c) ? 1.f : 0.f;
        for (int k = c; k < r; k++)
          acc -= s[(pc + r) * SPITCH + pc + k] * li[(pc + k) * SPITCH + pc + c];
        li[(pc + r) * SPITCH + pc + c] = acc * dinv[pc + r];
      }
    } else if (tid - 32 < nrows) {
      // (c) per-row forward substitution for rows below; also fill ls (transposed)
      int rloc = tid - 32;
      int rr = pc + 32 + rloc;
      #pragma unroll 1
      for (int j = 0; j < 32; j++) {
        float val = s[rr * SPITCH + pc + j];
        for (int k = 0; k < j; k++)
          val -= s[rr * SPITCH + pc + k] * s[(pc + j) * SPITCH + pc + k];
        val *= dinv[pc + j];
        s[rr * SPITCH + pc + j] = val;
        ls[j * 100 + rloc] = val;
      }
    }
    __syncthreads();

    // (d) rank-32 trailing update, LOWER tiles only, float4 reads from ls
    if (nrows > 0) {
      int base = pc + 32;
      int nt = nrows >> 2;
      int ntile = nt * (nt + 1) / 2;
      for (int t = tid; t < ntile; t += 512) {
        int ti = (int)((sqrtf(8.f * (float)t + 1.f) - 1.f) * 0.5f);
        while ((ti + 1) * (ti + 2) / 2 <= t) ti++;
        while (ti * (ti + 1) / 2 > t) ti--;
        int tj = t - ti * (ti + 1) / 2;
        float acc[4][4] = {};
        #pragma unroll 8
        for (int k = 0; k < 32; k++) {
          float4 av = *(const float4*)&ls[k * 100 + ti * 4];
          float4 bv = *(const float4*)&ls[k * 100 + tj * 4];
          float ar[4] = {av.x, av.y, av.z, av.w};
          float br[4] = {bv.x, bv.y, bv.z, bv.w};
          #pragma unroll
          for (int i = 0; i < 4; i++)
            #pragma unroll
            for (int j = 0; j < 4; j++)
              acc[i][j] += ar[i] * br[j];
        }
        int tr = base + ti * 4, tc = base + tj * 4;
        #pragma unroll
        for (int i = 0; i < 4; i++)
          #pragma unroll
          for (int j = 0; j < 4; j++)
            s[(tr + i) * SPITCH + tc + j] -= acc[i][j];
      }
    }
    __syncthreads();
  }

  // assemble off-diagonal blocks of inv(L11): stages by block-diagonal distance
  {
    const int s_begin[4] = {0, 3, 5, 6};
    const int prs[6] = {1, 2, 3, 2, 3, 3};
    const int pcs[6] = {0, 1, 2, 0, 1, 0};
    for (int st = 0; st < 3; st++) {
      int e0 = s_begin[st], e1 = s_begin[st + 1];
      int np = e1 - e0;
      // phase A: T_e = sum_k L_{r,k} * Linv_{k,c} stashed in (c,r) upper slot
      for (int t = tid; t < np * 1024; t += 512) {
        int e = e0 + (t >> 10);
        int cell = t & 1023;
        int i = cell >> 5, j = cell & 31;
        int r = prs[e], c = pcs[e];
        float acc = 0.f;
        for (int kb2 = c; kb2 < r; kb2++)
          #pragma unroll 8
          for (int k = 0; k < 32; k++)
            acc += s[(32 * r + i) * SPITCH + 32 * kb2 + k] * li[(32 * kb2 + k) * SPITCH + 32 * c + j];
        li[(32 * c + i) * SPITCH + 32 * r + j] = acc;
      }
      __syncthreads();
      // phase B: Linv_{r,c} = -Linv_{r,r} * T   (reads (c,r)-slot, writes (r,c)-slot)
      for (int t = tid; t < np * 1024; t += 512) {
        int e = e0 + (t >> 10);
        int cell = t & 1023;
        int i = cell >> 5, j = cell & 31;
        int r = prs[e], c = pcs[e];
        float acc = 0.f;
        #pragma unroll 8
        for (int k = 0; k < 32; k++)
          acc += li[(32 * r + i) * SPITCH + 32 * r + k] * li[(32 * c + k) * SPITCH + 32 * r + j];
        li[(32 * r + i) * SPITCH + 32 * c + j] = -acc;
      }
      __syncthreads();
    }
    // zero the scratch (upper) region so stored Linv is exactly lower-triangular
    for (int idx = tid; idx < 128 * 128; idx += 512) {
      int r = idx >> 7, c = idx & 127;
      if (c > r) li[r * SPITCH + c] = 0.f;
    }
    __syncthreads();
  }

  // logdet contribution
  if (tid < 128) lg[tid] = logf(s[tid * SPITCH + tid]);
  __syncthreads();
  if (tid == 0) {
    double acc = 0.0;
    for (int j = 0; j < 128; j++) acc += (double)lg[j];
    atomicAdd(&g_red[2], acc);
  }

  // store L (lower+diag) and Linv
  for (int idx = tid; idx < 128 * 128; idx += 512) {
    int r = idx >> 7, c = idx & 127;
    if (c <= r) g_A[(size_t)(k0 + r) * Q + k0 + c] = s[r * SPITCH + c];
    g_Linv[kb * 16384 + idx] = li[r * SPITCH + c];
  }
}

// ---------------- 64x64 GEMM core (K=128), 128 threads, 8x4 micro ----------
__device__ __forceinline__ void gemm64_core(const float* __restrict__ aRow, int lda,
                                            const float* __restrict__ bRow, int ldb,
                                            float (*as)[68], float (*bs)[68],
                                            float acc[8][4]) {
  int tid = threadIdx.x;
  int tx = tid & 15, ty = tid >> 4;
  for (int kk = 0; kk < 128; kk += 16) {
    #pragma unroll
    for (int i2 = 0; i2 < 2; i2++) {
      int li = tid + i2 * 128;
      int r = li >> 2, c4 = li & 3;
      float4 va = *(const float4*)(aRow + (size_t)r * lda + kk + c4 * 4);
      float4 vb = *(const float4*)(bRow + (size_t)r * ldb + kk + c4 * 4);
      as[c4 * 4 + 0][r] = va.x; as[c4 * 4 + 1][r] = va.y;
      as[c4 * 4 + 2][r] = va.z; as[c4 * 4 + 3][r] = va.w;
      bs[c4 * 4 + 0][r] = vb.x; bs[c4 * 4 + 1][r] = vb.y;
      bs[c4 * 4 + 2][r] = vb.z; bs[c4 * 4 + 3][r] = vb.w;
    }
    __syncthreads();
    #pragma unroll
    for (int k = 0; k < 16; k++) {
      float4 A0 = *(const float4*)&as[k][ty * 8];
      float4 A1 = *(const float4*)&as[k][ty * 8 + 4];
      float4 B0 = *(const float4*)&bs[k][tx * 4];
      float ar[8] = {A0.x, A0.y, A0.z, A0.w, A1.x, A1.y, A1.z, A1.w};
      float br[4] = {B0.x, B0.y, B0.z, B0.w};
      #pragma unroll
      for (int i = 0; i < 8; i++)
        #pragma unroll
        for (int j = 0; j < 4; j++)
          acc[i][j] += ar[i] * br[j];
    }
    __syncthreads();
  }
}

// trsm: X = A21 * Linv^T  ->  g_X   (grid: x=2 col tiles, y=2*rem row tiles)
__global__ void __launch_bounds__(128) k_trsm64(int k0, int kb) {
  __shared__ float as[16][68], bs[16][68];
  int bx = blockIdx.x, by = blockIdx.y;
  const float* aRow = g_A + (size_t)(k0 + 128 + by * 64) * Q + k0;
  const float* bRow = g_Linv + kb * 16384 + bx * 64 * 128;
  float acc[8][4] = {};
  gemm64_core(aRow, Q, bRow, 128, as, bs, acc);
  int tx = threadIdx.x & 15, ty = threadIdx.x >> 4;
  #pragma unroll
  for (int i = 0; i < 8; i++) {
    float4 v = {acc[i][0], acc[i][1], acc[i][2], acc[i][3]};
    *(float4*)(g_X + (size_t)(by * 64 + ty * 8 + i) * 128 + bx * 64 + tx * 4) = v;
  }
}

// syrk: A22 -= X * X^T (lower tiles only); diagonal CTAs also copy L21 back
__global__ void __launch_bounds__(128) k_syrk64(int k0) {
  int bx = blockIdx.x, by = blockIdx.y;
  if (by < bx) return;
  __shared__ float as[16][68], bs[16][68];
  int tid = threadIdx.x;
  if (bx == by) {
    for (int i = tid; i < 64 * 32; i += 128) {
      int r = i >> 5, c4 = i & 31;
      float4 v = *(const float4*)(g_X + (size_t)(by * 64 + r) * 128 + c4 * 4);
      *(float4*)(g_A + (size_t)(k0 + 128 + by * 64 + r) * Q + k0 + c4 * 4) = v;
    }
  }
  const float* aRow = g_X + (size_t)by * 64 * 128;
  const float* bRow = g_X + (size_t)bx * 64 * 128;
  float acc[8][4] = {};
  gemm64_core(aRow, 128, bRow, 128, as, bs, acc);
  int tx = tid & 15, ty = tid >> 4;
  #pragma unroll
  for (int i = 0; i < 8; i++) {
    float* cp = g_A + (size_t)(k0 + 128 + by * 64 + ty * 8 + i) * Q + (k0 + 128) + bx * 64 + tx * 4;
    float4 v = *(float4*)cp;
    v.x -= acc[i][0]; v.y -= acc[i][1]; v.z -= acc[i][2]; v.w -= acc[i][3];
    *(float4*)cp = v;
  }
}

// ---------------- forward solve + final assembly (single CTA, 1024 thr) ----
__global__ void k_solve(float* __restrict__ out, const float* __restrict__ pe,
                        const float* __restrict__ pb, int n) {
  float* vbuf = sh;         // Q
  float* ybuf = sh + Q;     // Q
  __shared__ double dred[32];
  int tid = threadIdx.x;

  for (int i = tid; i < Q; i += 1024) vbuf[i] = g_v[i];
  __syncthreads();

  double pv = 0.0;
  for (int i = tid; i < Q; i += 1024) { double t = vbuf[i]; pv += t * t; }
  double vtv = block_reduce_1024(pv, dred);

  int row = tid >> 3, lane8 = tid & 7;
  for (int b = 0; b < NBLK; b++) {
    int c0 = b * NB;
    const float* Li = g_Linv + b * 16384;
    float acc = 0.f;
    #pragma unroll
    for (int k4 = 0; k4 < 4; k4++) {
      int k = lane8 * 16 + k4 * 4;
      float4 a = *(const float4*)(Li + row * 128 + k);
      float4 v = *(const float4*)(&vbuf[c0 + k]);
      acc += a.x * v.x + a.y * v.y + a.z * v.z + a.w * v.w;
    }
    #pragma unroll
    for (int o = 4; o; o >>= 1) acc += __shfl_down_sync(0xffffffffu, acc, o, 8);
    if (lane8 == 0) ybuf[c0 + row] = acc;
    __syncthreads();
    for (int i = c0 + NB + tid; i < Q; i += 1024) {
      const float4* Ar = (const float4*)&g_A[(size_t)i * Q + c0];
      const float4* yb = (const float4*)&ybuf[c0];
      float d = 0.f;
      #pragma unroll
      for (int j4 = 0; j4 < 32; j4++) {
        float4 a = Ar[j4], y = yb[j4];
        d += a.x * y.x + a.y * y.y + a.z * y.z + a.w * y.w;
      }
      vbuf[i] -= d;
    }
    __syncthreads();
  }

  double py = 0.0;
  for (int i = tid; i < Q; i += 1024) { double t = ybuf[i]; py += t * t; }
  double yty = block_reduce_1024(py, dred);

  if (tid == 0) {
    double mtm = g_red[0], sumR2 = g_red[1], logdetA = 2.0 * g_red[2];
    double s2e = (double)pe[0], s2b = (double)pb[0], s2 = s2e + s2b;
    double dn = (double)n;
    double logdetR = (dn - (double)Q) * log(s2e) + logdetA - dn * log(s2);
    double mVm = (mtm - vtv + s2e * yty) / s2e;
    double slp = -0.5 * dn * log(6.283185307179586 * s2) - sumR2 / (2.0 * s2);
    double total = 0.5 * logdetR + 0.5 * s2 * mVm - 0.5 * mtm + 0.5 * slp;
    out[0] = (float)total;
  }
}

// ---------------- host ----------------
extern "C" void kernel_launch(void* const* d_in, const int* in_sizes, int n_in,
                              void* d_out, int out_size) {
  const float* y_true = (const float*)d_in[0];
  const float* y_pred = (const float*)d_in[1];
  const int*   Z_idx  = (const int*)  d_in[2];
  const float* dist   = (const float*)d_in[3];
  const float* s2e    = (const float*)d_in[4];
  const float* s2b    = (const float*)d_in[5];
  const float* ell    = (const float*)d_in[6];
  int n = in_sizes[0];

  size_t potf_smem  = (size_t)(2 * 128 * SPITCH + 32 * 100 + 256) * sizeof(float);
  size_t solve_smem = (size_t)(2 * Q) * sizeof(float);
  cudaFuncSetAttribute(k_potf,  cudaFuncAttributeMaxDynamicSharedMemorySize, (int)potf_smem);
  cudaFuncSetAttribute(k_solve, cudaFuncAttributeMaxDynamicSharedMemorySize, (int)solve_smem);

  k_reset<<<(Q + 255) / 256, 256>>>();
  k_obs<<<(n + 255) / 256, 256>>>(y_true, y_pred, Z_idx, s2e, s2b, n);
  k_v<<<(Q + 255) / 256, 256>>>();
  k_build<<<(Q * Q / 4) / 256, 256>>>(dist, s2e, s2b, ell);

  for (int kb = 0; kb < NBLK; kb++) {
    int k0 = kb * NB;
    k_potf<<<1, 512, potf_smem>>>(k0, kb);
    int rem = NBLK - 1 - kb;
    if (rem > 0) {
      dim3 gt(2, 2 * rem);
      k_trsm64<<<gt, 128>>>(k0, kb);
      dim3 gs(2 * rem, 2 * rem);
      k_syrk64<<<gs, 128>>>(k0);
    }
  }
  k_solve<<<1, 1024, solve_smem>>>((float*)d_out, s2e, s2b, n);
}

// round 6
// speedup vs baseline: 1.0967x; 1.0967x over previous
#include <cuda_runtime.h>
#include <cstdint>
#include <cstddef>

#define Q    2048
#define NB   128
#define NBLK (Q/NB)
#define SPITCH 129

// ---------------- scratch (device globals; no allocations allowed) ----------
__device__ float  g_A[Q*Q];                 // working matrix / Cholesky factor
__device__ float  g_Linv[NBLK*NB*NB];       // per-panel inverse of diag block
__device__ float  g_X0[(Q-NB)*NB];          // trsm staging buffer (parity 0)
__device__ float  g_X1[(Q-NB)*NB];          // trsm staging buffer (parity 1)
__device__ float  g_w[Q];
__device__ int    g_cnt[Q];
__device__ float  g_v[Q];
__device__ float  g_sc[Q];
__device__ double g_red[4];                 // [0]=m'm [1]=sum r^2 [2]=sum log Lkk

// ---------------- reductions ----------------
__device__ __forceinline__ double block_reduce_1024(double v, double* scratch) {
  #pragma unroll
  for (int o = 16; o; o >>= 1) v += __shfl_down_sync(0xffffffffu, v, o);
  if ((threadIdx.x & 31) == 0) scratch[threadIdx.x >> 5] = v;
  __syncthreads();
  double r = 0.0;
  if (threadIdx.x < 32) {
    r = scratch[threadIdx.x];
    #pragma unroll
    for (int o = 16; o; o >>= 1) r += __shfl_down_sync(0xffffffffu, r, o);
  }
  __syncthreads();
  return r;   // valid on thread 0
}

// ---------------- small kernels ----------------
__global__ void k_reset() {
  int i = blockIdx.x * blockDim.x + threadIdx.x;
  if (i < Q) { g_w[i] = 0.f; g_cnt[i] = 0; }
  if (i < 4) g_red[i] = 0.0;
}

__global__ void k_obs(const float* __restrict__ yt, const float* __restrict__ yp,
                      const int* __restrict__ z,
                      const float* __restrict__ pe, const float* __restrict__ pb, int n) {
  int i = blockIdx.x * blockDim.x + threadIdx.x;
  float m = 0.f, r = 0.f;
  if (i < n) {
    r = yt[i] - yp[i];
    float s2 = pe[0] + pb[0];
    float u  = 0.5f * (erff(r / sqrtf(2.f * s2)) + 1.f);
    u = fminf(fmaxf(u, 1e-5f), 1.f - 1e-5f);
    m = erfinvf(2.f * u - 1.f) * 1.41421356237309515f;
    atomicAdd(&g_cnt[z[i]], 1);
    atomicAdd(&g_w[z[i]], m);
  }
  double mm = (double)m * (double)m;
  double rr = (double)r * (double)r;
  #pragma unroll
  for (int o = 16; o; o >>= 1) {
    mm += __shfl_down_sync(0xffffffffu, mm, o);
    rr += __shfl_down_sync(0xffffffffu, rr, o);
  }
  if ((threadIdx.x & 31) == 0) { atomicAdd(&g_red[0], mm); atomicAdd(&g_red[1], rr); }
}

__global__ void k_v() {
  int i = blockIdx.x * blockDim.x + threadIdx.x;
  if (i < Q) {
    int c = g_cnt[i];
    float sc = sqrtf((float)c);
    g_sc[i] = sc;
    g_v[i]  = (c > 0) ? g_w[i] / sc : 0.f;
  }
}

// A[i,j] = sqrt(c_i c_j) * sig2b * exp(-dist/(2 ell)) + (i==j) sig2e
__global__ void k_build(const float* __restrict__ dist, const float* __restrict__ pe,
                        const float* __restrict__ pb, const float* __restrict__ pl) {
  int idx = blockIdx.x * 256 + threadIdx.x;      // over Q*Q/4
  int i  = idx >> 9;                              // Q/4 = 512 float4 per row
  int j4 = idx & 511;
  float inv2l = 0.5f / pl[0];
  float sci = g_sc[i] * pb[0];
  int j = j4 * 4;
  float4 d = *(const float4*)(dist + (size_t)i * Q + j);
  float4 o;
  o.x = sci * g_sc[j + 0] * expf(-d.x * inv2l);
  o.y = sci * g_sc[j + 1] * expf(-d.y * inv2l);
  o.z = sci * g_sc[j + 2] * expf(-d.z * inv2l);
  o.w = sci * g_sc[j + 3] * expf(-d.w * inv2l);
  if (i >= j && i < j + 4) ((float*)&o)[i - j] += pe[0];
  *(float4*)(g_A + (size_t)i * Q + j) = o;
}

// ---------------- panel factorization: L11, inv(L11), logdet -------------
// 512 threads. smem: s[128*129], li[128*129], dinv[128], lg[128]
extern __shared__ float sh[];

__global__ void k_potf(int k0, int kb) {
  float* s    = sh;                       // 128*129
  float* li   = sh + 128 * SPITCH;        // 128*129
  float* dinv = li + 128 * SPITCH;        // 128
  float* lg   = dinv + 128;               // 128
  int tid = threadIdx.x;
  int warp = tid >> 5, lane = tid & 31;

  for (int idx = tid; idx < 128 * 128; idx += 512) {
    int r = idx >> 7, c = idx & 127;
    s[r * SPITCH + c]  = g_A[(size_t)(k0 + r) * Q + k0 + c];
    li[r * SPITCH + c] = 0.f;
  }
  __syncthreads();

  #pragma unroll 1
  for (int p = 0; p < 4; p++) {
    int pc = p * 32;
    // (a) warp 0 factors 32x32 diagonal sub-block (lane owns row, syncwarp only)
    if (warp == 0) {
      int rr = pc + lane;
      #pragma unroll 1
      for (int j = 0; j < 32; j++) {
        int jj = pc + j;
        float d   = sqrtf(s[jj * SPITCH + jj]);
        float inv = 1.f / d;
        __syncwarp();
        if (lane == j) { s[jj * SPITCH + jj] = d; dinv[jj] = inv; }
        if (lane > j)  s[rr * SPITCH + jj] *= inv;
        __syncwarp();
        if (lane > j) {
          float lij = s[rr * SPITCH + jj];
          for (int k = j + 1; k <= lane; k++)
            s[rr * SPITCH + pc + k] -= lij * s[(pc + k) * SPITCH + jj];
        }
        __syncwarp();
      }
    }
    __syncthreads();
    int nrows = 96 - pc;   // rows below this sub-panel within the 128 block
    // (b) warp 0: invert 32x32 diag sub-block (per-lane column)
    if (warp == 0) {
      int c = lane;
      #pragma unroll 1
      for (int r = c; r < 32; r++) {
        float acc = (r == c) ? 1.f : 0.f;
        for (int k = c; k < r; k++)
          acc -= s[(pc + r) * SPITCH + pc + k] * li[(pc + k) * SPITCH + pc + c];
        li[(pc + r) * SPITCH + pc + c] = acc * dinv[pc + r];
      }
    } else if (tid - 32 < nrows) {
      // (c) per-row forward substitution for rows below (parallel over rows)
      int rr = pc + 32 + (tid - 32);
      #pragma unroll 1
      for (int j = 0; j < 32; j++) {
        float val = s[rr * SPITCH + pc + j];
        for (int k = 0; k < j; k++)
          val -= s[rr * SPITCH + pc + k] * s[(pc + j) * SPITCH + pc + k];
        s[rr * SPITCH + pc + j] = val * dinv[pc + j];
      }
    }
    __syncthreads();
    // (d) rank-32 trailing update within the 128 block (4x4 micro-tiles)
    if (nrows > 0) {
      int base = pc + 32;
      int nt = nrows >> 2;
      for (int t = tid; t < nt * nt; t += 512) {
        int tr = base + (t / nt) * 4;
        int tc = base + (t % nt) * 4;
        float acc[4][4] = {};
        #pragma unroll 8
        for (int k = 0; k < 32; k++) {
          float a0 = s[(tr + 0) * SPITCH + pc + k], a1 = s[(tr + 1) * SPITCH + pc + k];
          float a2 = s[(tr + 2) * SPITCH + pc + k], a3 = s[(tr + 3) * SPITCH + pc + k];
          float b0 = s[(tc + 0) * SPITCH + pc + k], b1 = s[(tc + 1) * SPITCH + pc + k];
          float b2 = s[(tc + 2) * SPITCH + pc + k], b3 = s[(tc + 3) * SPITCH + pc + k];
          acc[0][0] += a0 * b0; acc[0][1] += a0 * b1; acc[0][2] += a0 * b2; acc[0][3] += a0 * b3;
          acc[1][0] += a1 * b0; acc[1][1] += a1 * b1; acc[1][2] += a1 * b2; acc[1][3] += a1 * b3;
          acc[2][0] += a2 * b0; acc[2][1] += a2 * b1; acc[2][2] += a2 * b2; acc[2][3] += a2 * b3;
          acc[3][0] += a3 * b0; acc[3][1] += a3 * b1; acc[3][2] += a3 * b2; acc[3][3] += a3 * b3;
        }
        #pragma unroll
        for (int i = 0; i < 4; i++)
          #pragma unroll
          for (int j = 0; j < 4; j++)
            s[(tr + i) * SPITCH + tc + j] -= acc[i][j];
      }
    }
    __syncthreads();
  }

  // assemble off-diagonal blocks of inv(L11): stages by block-diagonal distance
  {
    const int s_begin[4] = {0, 3, 5, 6};
    const int prs[6] = {1, 2, 3, 2, 3, 3};
    const int pcs[6] = {0, 1, 2, 0, 1, 0};
    for (int st = 0; st < 3; st++) {
      int e0 = s_begin[st], e1 = s_begin[st + 1];
      int np = e1 - e0;
      // phase A: T_e = sum_k L_{r,k} * Linv_{k,c} stashed in (c,r) upper slot
      for (int t = tid; t < np * 1024; t += 512) {
        int e = e0 + (t >> 10);
        int cell = t & 1023;
        int i = cell >> 5, j = cell & 31;
        int r = prs[e], c = pcs[e];
        float acc = 0.f;
        for (int kb2 = c; kb2 < r; kb2++)
          #pragma unroll 8
          for (int k = 0; k < 32; k++)
            acc += s[(32 * r + i) * SPITCH + 32 * kb2 + k] * li[(32 * kb2 + k) * SPITCH + 32 * c + j];
        li[(32 * c + i) * SPITCH + 32 * r + j] = acc;
      }
      __syncthreads();
      // phase B: Linv_{r,c} = -Linv_{r,r} * T   (reads (c,r)-slot, writes (r,c)-slot)
      for (int t = tid; t < np * 1024; t += 512) {
        int e = e0 + (t >> 10);
        int cell = t & 1023;
        int i = cell >> 5, j = cell & 31;
        int r = prs[e], c = pcs[e];
        float acc = 0.f;
        #pragma unroll 8
        for (int k = 0; k < 32; k++)
          acc += li[(32 * r + i) * SPITCH + 32 * r + k] * li[(32 * c + k) * SPITCH + 32 * r + j];
        li[(32 * r + i) * SPITCH + 32 * c + j] = -acc;
      }
      __syncthreads();
    }
    // zero the scratch (upper) region so stored Linv is exactly lower-triangular
    for (int idx = tid; idx < 128 * 128; idx += 512) {
      int r = idx >> 7, c = idx & 127;
      if (c > r) li[r * SPITCH + c] = 0.f;
    }
    __syncthreads();
  }

  // logdet contribution
  if (tid < 128) lg[tid] = logf(s[tid * SPITCH + tid]);
  __syncthreads();
  if (tid == 0) {
    double acc = 0.0;
    for (int j = 0; j < 128; j++) acc += (double)lg[j];
    atomicAdd(&g_red[2], acc);
  }

  // store L (lower+diag) and Linv
  for (int idx = tid; idx < 128 * 128; idx += 512) {
    int r = idx >> 7, c = idx & 127;
    if (c <= r) g_A[(size_t)(k0 + r) * Q + k0 + c] = s[r * SPITCH + c];
    g_Linv[kb * 16384 + idx] = li[r * SPITCH + c];
  }
}

// ---------------- 64x64 GEMM core (K=128), 128 threads, 8x4 micro ----------
__device__ __forceinline__ void gemm64_core(const float* __restrict__ aRow, int lda,
                                            const float* __restrict__ bRow, int ldb,
                                            float (*as)[68], float (*bs)[68],
                                            float acc[8][4]) {
  int tid = threadIdx.x;
  int tx = tid & 15, ty = tid >> 4;
  for (int kk = 0; kk < 128; kk += 16) {
    #pragma unroll
    for (int i2 = 0; i2 < 2; i2++) {
      int li = tid + i2 * 128;
      int r = li >> 2, c4 = li & 3;
      float4 va = *(const float4*)(aRow + (size_t)r * lda + kk + c4 * 4);
      float4 vb = *(const float4*)(bRow + (size_t)r * ldb + kk + c4 * 4);
      as[c4 * 4 + 0][r] = va.x; as[c4 * 4 + 1][r] = va.y;
      as[c4 * 4 + 2][r] = va.z; as[c4 * 4 + 3][r] = va.w;
      bs[c4 * 4 + 0][r] = vb.x; bs[c4 * 4 + 1][r] = vb.y;
      bs[c4 * 4 + 2][r] = vb.z; bs[c4 * 4 + 3][r] = vb.w;
    }
    __syncthreads();
    #pragma unroll
    for (int k = 0; k < 16; k++) {
      float4 A0 = *(const float4*)&as[k][ty * 8];
      float4 A1 = *(const float4*)&as[k][ty * 8 + 4];
      float4 B0 = *(const float4*)&bs[k][tx * 4];
      float ar[8] = {A0.x, A0.y, A0.z, A0.w, A1.x, A1.y, A1.z, A1.w};
      float br[4] = {B0.x, B0.y, B0.z, B0.w};
      #pragma unroll
      for (int i = 0; i < 8; i++)
        #pragma unroll
        for (int j = 0; j < 4; j++)
          acc[i][j] += ar[i] * br[j];
    }
    __syncthreads();
  }
}

// trsm: X = A21 * Linv^T  ->  xbuf (xsel-selected) (grid: x=2 col tiles, y=2*rem rows)
__global__ void __launch_bounds__(128) k_trsm64(int k0, int kb, int xsel) {
  float* xbuf = xsel ? g_X1 : g_X0;
  __shared__ float as[16][68], bs[16][68];
  int bx = blockIdx.x, by = blockIdx.y;
  const float* aRow = g_A + (size_t)(k0 + 128 + by * 64) * Q + k0;
  const float* bRow = g_Linv + kb * 16384 + bx * 64 * 128;
  float acc[8][4] = {};
  gemm64_core(aRow, Q, bRow, 128, as, bs, acc);
  int tx = threadIdx.x & 15, ty = threadIdx.x >> 4;
  #pragma unroll
  for (int i = 0; i < 8; i++) {
    float4 v = {acc[i][0], acc[i][1], acc[i][2], acc[i][3]};
    *(float4*)(xbuf + (size_t)(by * 64 + ty * 8 + i) * 128 + bx * 64 + tx * 4) = v;
  }
}

// syrk: A22 -= X * X^T (lower tiles only); diagonal CTAs also copy L21 back.
// bxOff splits the grid into panel (bxOff=0, 2 cols) and rest (bxOff=2).
__global__ void __launch_bounds__(128) k_syrk64(int k0, int bxOff, int xsel) {
  const float* xbuf = xsel ? g_X1 : g_X0;
  int bx = blockIdx.x + bxOff, by = blockIdx.y;
  if (by < bx) return;
  __shared__ float as[16][68], bs[16][68];
  int tid = threadIdx.x;
  if (bx == by) {
    for (int i = tid; i < 64 * 32; i += 128) {
      int r = i >> 5, c4 = i & 31;
      float4 v = *(const float4*)(xbuf + (size_t)(by * 64 + r) * 128 + c4 * 4);
      *(float4*)(g_A + (size_t)(k0 + 128 + by * 64 + r) * Q + k0 + c4 * 4) = v;
    }
  }
  const float* aRow = xbuf + (size_t)by * 64 * 128;
  const float* bRow = xbuf + (size_t)bx * 64 * 128;
  float acc[8][4] = {};
  gemm64_core(aRow, 128, bRow, 128, as, bs, acc);
  int tx = tid & 15, ty = tid >> 4;
  #pragma unroll
  for (int i = 0; i < 8; i++) {
    float* cp = g_A + (size_t)(k0 + 128 + by * 64 + ty * 8 + i) * Q + (k0 + 128) + bx * 64 + tx * 4;
    float4 v = *(float4*)cp;
    v.x -= acc[i][0]; v.y -= acc[i][1]; v.z -= acc[i][2]; v.w -= acc[i][3];
    *(float4*)cp = v;
  }
}

// ---------------- forward solve + final assembly (single CTA, 1024 thr) ----
__global__ void k_solve(float* __restrict__ out, const float* __restrict__ pe,
                        const float* __restrict__ pb, int n) {
  float* vbuf = sh;         // Q
  float* ybuf = sh + Q;     // Q
  __shared__ double dred[32];
  int tid = threadIdx.x;

  for (int i = tid; i < Q; i += 1024) vbuf[i] = g_v[i];
  __syncthreads();

  double pv = 0.0;
  for (int i = tid; i < Q; i += 1024) { double t = vbuf[i]; pv += t * t; }
  double vtv = block_reduce_1024(pv, dred);

  int row = tid >> 3, lane8 = tid & 7;
  for (int b = 0; b < NBLK; b++) {
    int c0 = b * NB;
    const float* Li = g_Linv + b * 16384;
    float acc = 0.f;
    #pragma unroll
    for (int k4 = 0; k4 < 4; k4++) {
      int k = lane8 * 16 + k4 * 4;
      float4 a = *(const float4*)(Li + row * 128 + k);
      float4 v = *(const float4*)(&vbuf[c0 + k]);
      acc += a.x * v.x + a.y * v.y + a.z * v.z + a.w * v.w;
    }
    #pragma unroll
    for (int o = 4; o; o >>= 1) acc += __shfl_down_sync(0xffffffffu, acc, o, 8);
    if (lane8 == 0) ybuf[c0 + row] = acc;
    __syncthreads();
    for (int i = c0 + NB + tid; i < Q; i += 1024) {
      const float4* Ar = (const float4*)&g_A[(size_t)i * Q + c0];
      const float4* yb = (const float4*)&ybuf[c0];
      float d = 0.f;
      #pragma unroll
      for (int j4 = 0; j4 < 32; j4++) {
        float4 a = Ar[j4], y = yb[j4];
        d += a.x * y.x + a.y * y.y + a.z * y.z + a.w * y.w;
      }
      vbuf[i] -= d;
    }
    __syncthreads();
  }

  double py = 0.0;
  for (int i = tid; i < Q; i += 1024) { double t = ybuf[i]; py += t * t; }
  double yty = block_reduce_1024(py, dred);

  if (tid == 0) {
    double mtm = g_red[0], sumR2 = g_red[1], logdetA = 2.0 * g_red[2];
    double s2e = (double)pe[0], s2b = (double)pb[0], s2 = s2e + s2b;
    double dn = (double)n;
    double logdetR = (dn - (double)Q) * log(s2e) + logdetA - dn * log(s2);
    double mVm = (mtm - vtv + s2e * yty) / s2e;
    double slp = -0.5 * dn * log(6.283185307179586 * s2) - sumR2 / (2.0 * s2);
    double total = 0.5 * logdetR + 0.5 * s2 * mVm - 0.5 * mtm + 0.5 * slp;
    out[0] = (float)total;
  }
}

// ---------------- streams/events for lookahead (created once, pre-checkpoint) ----
static cudaStream_t g_s1 = 0;
static cudaEvent_t  g_evT[NBLK];
static cudaEvent_t  g_evR[NBLK];
namespace {
struct StreamInit {
  StreamInit() {
    if (cudaStreamCreateWithFlags(&g_s1, cudaStreamNonBlocking) != cudaSuccess) g_s1 = 0;
    for (int i = 0; i < NBLK; i++) {
      cudaEventCreateWithFlags(&g_evT[i], cudaEventDisableTiming);
      cudaEventCreateWithFlags(&g_evR[i], cudaEventDisableTiming);
    }
  }
};
StreamInit g_streamInit;
}

// ---------------- host ----------------
extern "C" void kernel_launch(void* const* d_in, const int* in_sizes, int n_in,
                              void* d_out, int out_size) {
  const float* y_true = (const float*)d_in[0];
  const float* y_pred = (const float*)d_in[1];
  const int*   Z_idx  = (const int*)  d_in[2];
  const float* dist   = (const float*)d_in[3];
  const float* s2e    = (const float*)d_in[4];
  const float* s2b    = (const float*)d_in[5];
  const float* ell    = (const float*)d_in[6];
  int n = in_sizes[0];

  size_t potf_smem  = (size_t)(2 * 128 * SPITCH + 256) * sizeof(float);
  size_t solve_smem = (size_t)(2 * Q) * sizeof(float);
  cudaFuncSetAttribute(k_potf,  cudaFuncAttributeMaxDynamicSharedMemorySize, (int)potf_smem);
  cudaFuncSetAttribute(k_solve, cudaFuncAttributeMaxDynamicSharedMemorySize, (int)solve_smem);

  k_reset<<<(Q + 255) / 256, 256>>>();
  k_obs<<<(n + 255) / 256, 256>>>(y_true, y_pred, Z_idx, s2e, s2b, n);
  k_v<<<(Q + 255) / 256, 256>>>();
  k_build<<<(Q * Q / 4) / 256, 256>>>(dist, s2e, s2b, ell);

  for (int kb = 0; kb < NBLK; kb++) {
    int k0 = kb * NB;
    k_potf<<<1, 512, potf_smem>>>(k0, kb);
    int rem = NBLK - 1 - kb;
    if (rem > 0) {
      int xsel = kb & 1;
      // trsm: safe WAR on xbuf[xsel] because s0 already waited evR[kb-2]
      // (transitively via syrk_panel(kb-1)'s wait).
      k_trsm64<<<dim3(2, 2 * rem), 128>>>(k0, kb, xsel);
      cudaEventRecord(g_evT[kb], 0);
      if (kb >= 1) cudaStreamWaitEvent(0, g_evR[kb - 1], 0);
      k_syrk64<<<dim3(2, 2 * rem), 128>>>(k0, 0, xsel);           // panel (bx 0..1)
      cudaStreamWaitEvent(g_s1, g_evT[kb], 0);
      if (2 * rem > 2)
        k_syrk64<<<dim3(2 * rem - 2, 2 * rem), 128, 0, g_s1>>>(k0, 2, xsel);  // rest
      cudaEventRecord(g_evR[kb], g_s1);
    }
  }
  cudaStreamWaitEvent(0, g_evR[NBLK - 2], 0);
  k_solve<<<1, 1024, solve_smem>>>((float*)d_out, s2e, s2b, n);
}